// round 5
// baseline (speedup 1.0000x reference)
#include <cuda_runtime.h>
#include <cstdint>
#include <math.h>

#define N_PIX  50176
#define C_FEAT 4224
#define C4     1056      // C_FEAT/4
#define NSEG   128
#define D_HID  1024
#define D_LOW  32
#define KSPLIT1 33
#define KSPLIT2 16
#define NBLK   196       // N_PIX / 256
#define NCB    33        // C_FEAT / 128

// ---------------- scratch (static device globals; all fully overwritten each call) ----------------
__device__ int   g_blockhist[NBLK * NSEG];
__device__ int   g_blockcls[NBLK * NSEG * 3];
__device__ int   g_blockbase[NBLK * NSEG];
__device__ int   g_counts[NSEG];
__device__ int   g_start[NSEG];
__device__ int   g_perm[N_PIX];
__device__ float g_feat[NSEG * C_FEAT];
__device__ float g_norm2p[NSEG * NCB];
__device__ int   g_lab[NSEG];
__device__ int   g_labeled[NSEG];
__device__ int   g_lab2[NSEG];
__device__ float g_part[KSPLIT1 * 128 * 1024];
__device__ float g_h1[128 * D_HID];
__device__ float g_h2[128 * D_HID];

// ---------------- per-block histogram (no global atomics, no pre-zero) ----------------
__global__ void hist_k(const int* __restrict__ sp, const int* __restrict__ y) {
    __shared__ int hc[NSEG];
    __shared__ int hcls[NSEG * 3];
    int t = threadIdx.x;
    int b = blockIdx.x;
    if (t < NSEG) hc[t] = 0;
    for (int i = t; i < NSEG * 3; i += 256) hcls[i] = 0;
    __syncthreads();
    int i = b * 256 + t;
    int s = sp[i];
    atomicAdd(&hc[s], 1);
    atomicAdd(&hcls[s * 3 + y[i]], 1);
    __syncthreads();
    if (t < NSEG) g_blockhist[b * NSEG + t] = hc[t];
    for (int i2 = t; i2 < NSEG * 3; i2 += 256) g_blockcls[b * NSEG * 3 + i2] = hcls[i2];
}

// ---------------- scan over block hists + labels ----------------
__global__ void scan_k() {
    __shared__ int sh[NSEG];
    int t = threadIdx.x;   // = segment
    int tot = 0;
    #pragma unroll 4
    for (int b = 0; b < NBLK; b++) tot += g_blockhist[b * NSEG + t];
    sh[t] = tot;
    __syncthreads();
    if (t == 0) {
        int acc = 0;
        for (int i = 0; i < NSEG; i++) { int c = sh[i]; sh[i] = acc; acc += c; }
    }
    __syncthreads();
    int startv = sh[t];
    g_counts[t] = tot;
    g_start[t] = startv;
    int run = startv;
    #pragma unroll 4
    for (int b = 0; b < NBLK; b++) {
        g_blockbase[b * NSEG + t] = run;
        run += g_blockhist[b * NSEG + t];
    }
    int c0 = 0, c1 = 0, c2 = 0;
    #pragma unroll 4
    for (int b = 0; b < NBLK; b++) {
        const int* p = &g_blockcls[b * NSEG * 3 + t * 3];
        c0 += p[0]; c1 += p[1]; c2 += p[2];
    }
    int l = 0, best = c0;
    if (c1 > best) { best = c1; l = 1; }
    if (c2 > best) { best = c2; l = 2; }
    int fb = (c2 > (tot >> 1)) ? 2 : ((c1 >= 1) ? 1 : 0);
    if (l == 0) l = fb;
    g_lab[t] = l;
    g_labeled[t] = (l != 0);
}

// ---------------- scatter pixels into per-segment contiguous ranges ----------------
__global__ void scatter_k(const int* __restrict__ sp) {
    __shared__ int hc[NSEG];
    int t = threadIdx.x;
    int b = blockIdx.x;
    if (t < NSEG) hc[t] = 0;
    __syncthreads();
    int i = b * 256 + t;
    int s = sp[i];
    int r = atomicAdd(&hc[s], 1);
    g_perm[g_blockbase[b * NSEG + s] + r] = i;
}

// ---------------- segment sum: grid (33 col-chunks, 128 segments), 128 thr ----------------
__global__ void __launch_bounds__(128) segsum_k(const float* __restrict__ pixfeat) {
    __shared__ int   rows[512];
    __shared__ float red[4][128];
    int tid = threadIdx.x;
    int ty = tid >> 5, lane = tid & 31;
    int s = blockIdx.y;
    int cb = blockIdx.x * 128;
    int st = g_start[s], cnt = g_counts[s];
    const float4* pf = (const float4*)pixfeat;
    int cb4 = cb >> 2;
    float4 acc = make_float4(0.f, 0.f, 0.f, 0.f);

    for (int c0 = 0; c0 < cnt; c0 += 512) {
        int clim = min(512, cnt - c0);
        __syncthreads();
        for (int i = tid; i < clim; i += 128) rows[i] = g_perm[st + c0 + i];
        __syncthreads();
        int main_end = clim & ~31;
        for (int g = 0; g < main_end; g += 32) {
            int base = g + ty * 8;
            float4 v[8];
            #pragma unroll
            for (int u = 0; u < 8; u++)
                v[u] = __ldcs(&pf[(size_t)rows[base + u] * C4 + cb4 + lane]);
            #pragma unroll
            for (int u = 0; u < 8; u++) {
                acc.x += v[u].x; acc.y += v[u].y; acc.z += v[u].z; acc.w += v[u].w;
            }
        }
        for (int j = main_end + ty; j < clim; j += 4) {
            float4 v = __ldcs(&pf[(size_t)rows[j] * C4 + cb4 + lane]);
            acc.x += v.x; acc.y += v.y; acc.z += v.z; acc.w += v.w;
        }
    }
    __syncthreads();
    red[ty][lane * 4 + 0] = acc.x;
    red[ty][lane * 4 + 1] = acc.y;
    red[ty][lane * 4 + 2] = acc.z;
    red[ty][lane * 4 + 3] = acc.w;
    __syncthreads();
    float sum = red[0][tid] + red[1][tid] + red[2][tid] + red[3][tid];
    float inv = 1.f / fmaxf((float)cnt, 1.f);
    float f = sum * inv;
    g_feat[s * C_FEAT + cb + tid] = f;
    __syncthreads();
    red[0][tid] = f * f;
    __syncthreads();
    for (int s2 = 64; s2 > 0; s2 >>= 1) {
        if (tid < s2) red[0][tid] += red[0][tid + s2];
        __syncthreads();
    }
    if (tid == 0) g_norm2p[s * NCB + blockIdx.x] = red[0][0];
}

// ---------------- affinity + label propagation: grid 64 blocks, rows {b, b+64} ----------------
__global__ void __launch_bounds__(128) aff_k() {
    __shared__ float4 a0s4[16], a1s4[16];
    __shared__ float4 bs4[128][17];
    __shared__ float  rn[128];
    __shared__ float  rv0[128], rv1[128];
    __shared__ int    ri0[128], ri1[128];
    int tid = threadIdx.x;
    int i0 = blockIdx.x, i1 = blockIdx.x + 64;

    {
        float n2 = 0.f;
        #pragma unroll
        for (int i = 0; i < NCB; i++) n2 += g_norm2p[tid * NCB + i];
        rn[tid] = rsqrtf(n2);
    }

    const float4* feat4 = (const float4*)g_feat;
    float acc0 = 0.f, acc1 = 0.f;

    for (int k0 = 0; k0 < C4; k0 += 16) {
        __syncthreads();
        if (tid < 16)       a0s4[tid]      = feat4[i0 * C4 + k0 + tid];
        else if (tid < 32)  a1s4[tid - 16] = feat4[i1 * C4 + k0 + (tid - 16)];
        #pragma unroll
        for (int i = 0; i < 16; i++) {
            int idx = tid + i * 128;
            int r = idx >> 4, c = idx & 15;
            bs4[r][c] = feat4[r * C4 + k0 + c];
        }
        __syncthreads();
        #pragma unroll
        for (int kk = 0; kk < 16; kk++) {
            float4 bv = bs4[tid][kk];
            float4 x = a0s4[kk];
            float4 yv = a1s4[kk];
            acc0 += x.x * bv.x + x.y * bv.y + x.z * bv.z + x.w * bv.w;
            acc1 += yv.x * bv.x + yv.y * bv.y + yv.z * bv.z + yv.w * bv.w;
        }
    }
    float rj = rn[tid];
    bool labj = (g_labeled[tid] != 0);
    float v0 = labj ? acc0 * rn[i0] * rj : -INFINITY;
    float v1 = labj ? acc1 * rn[i1] * rj : -INFINITY;

    rv0[tid] = v0; ri0[tid] = tid;
    rv1[tid] = v1; ri1[tid] = tid;
    __syncthreads();
    for (int s2 = 64; s2 > 0; s2 >>= 1) {
        if (tid < s2) {
            float a = rv0[tid + s2]; int ia = ri0[tid + s2];
            if (a > rv0[tid] || (a == rv0[tid] && ia < ri0[tid])) { rv0[tid] = a; ri0[tid] = ia; }
            float b = rv1[tid + s2]; int ib = ri1[tid + s2];
            if (b > rv1[tid] || (b == rv1[tid] && ib < ri1[tid])) { rv1[tid] = b; ri1[tid] = ib; }
        }
        __syncthreads();
    }
    if (tid == 0) {
        g_lab2[i0] = (!g_labeled[i0] && rv0[0] > 0.8f) ? g_lab[ri0[0]] : g_lab[i0];
        g_lab2[i1] = (!g_labeled[i1] && rv1[0] > 0.8f) ? g_lab[ri1[0]] : g_lab[i1];
    }
}

// ---------------- tf32 MMA GEMM (M=128), split-K partials, double-buffered ----------------
// fp32 bits fed directly to tf32 mma (truncation; error ~2^-10 rel, fine at 1e-3 tol)
__device__ __forceinline__ void mma8(float& c0, float& c1, float& c2, float& c3,
                                     unsigned a0, unsigned a1, unsigned a2, unsigned a3,
                                     unsigned b0, unsigned b1) {
    asm volatile(
        "mma.sync.aligned.m16n8k8.row.col.f32.tf32.tf32.f32 "
        "{%0,%1,%2,%3},{%4,%5,%6,%7},{%8,%9},{%0,%1,%2,%3};\n"
        : "+f"(c0), "+f"(c1), "+f"(c2), "+f"(c3)
        : "r"(a0), "r"(a1), "r"(a2), "r"(a3), "r"(b0), "r"(b1));
}

template<int NSUB>
__global__ void __launch_bounds__(256) gemm_tf32_k(const float* __restrict__ A,
                                                   const float* __restrict__ B,
                                                   float* __restrict__ part,
                                                   int N, int K, int ksteps) {
    const int BN = 8 * NSUB;
    const int BELE = (8 * BN) / 256;
    __shared__ unsigned As[128][9];
    __shared__ unsigned Bs[8][BN + 4];
    int tid = threadIdx.x;
    int warp = tid >> 5, lane = tid & 31;
    int grp = lane >> 2, tig = lane & 3;
    int n0 = blockIdx.x * BN;
    int k_begin = blockIdx.y * ksteps * 8;

    int ar = tid >> 1;
    int ac = (tid & 1) * 4;

    float c[NSUB][4];
    #pragma unroll
    for (int i = 0; i < NSUB; i++) { c[i][0] = c[i][1] = c[i][2] = c[i][3] = 0.f; }

    uint4 aReg = *(const uint4*)(A + (size_t)ar * K + k_begin + ac);
    unsigned bReg[BELE];
    #pragma unroll
    for (int e = 0; e < BELE; e++) {
        int idx = tid + e * 256;
        int kr = idx / BN, n = idx % BN;
        bReg[e] = __float_as_uint(B[(size_t)(k_begin + kr) * N + n0 + n]);
    }
    As[ar][ac + 0] = aReg.x; As[ar][ac + 1] = aReg.y;
    As[ar][ac + 2] = aReg.z; As[ar][ac + 3] = aReg.w;
    #pragma unroll
    for (int e = 0; e < BELE; e++) {
        int idx = tid + e * 256;
        Bs[idx / BN][idx % BN] = bReg[e];
    }
    __syncthreads();

    int row = 16 * warp + grp;
    for (int ks = 0; ks < ksteps; ks++) {
        if (ks + 1 < ksteps) {
            int kk = k_begin + (ks + 1) * 8;
            aReg = *(const uint4*)(A + (size_t)ar * K + kk + ac);
            #pragma unroll
            for (int e = 0; e < BELE; e++) {
                int idx = tid + e * 256;
                int kr = idx / BN, n = idx % BN;
                bReg[e] = __float_as_uint(B[(size_t)(kk + kr) * N + n0 + n]);
            }
        }
        unsigned a0 = As[row][tig];
        unsigned a1 = As[row + 8][tig];
        unsigned a2 = As[row][tig + 4];
        unsigned a3 = As[row + 8][tig + 4];
        #pragma unroll
        for (int ns = 0; ns < NSUB; ns++) {
            unsigned b0 = Bs[tig][ns * 8 + grp];
            unsigned b1 = Bs[tig + 4][ns * 8 + grp];
            mma8(c[ns][0], c[ns][1], c[ns][2], c[ns][3], a0, a1, a2, a3, b0, b1);
        }
        __syncthreads();
        if (ks + 1 < ksteps) {
            As[ar][ac + 0] = aReg.x; As[ar][ac + 1] = aReg.y;
            As[ar][ac + 2] = aReg.z; As[ar][ac + 3] = aReg.w;
            #pragma unroll
            for (int e = 0; e < BELE; e++) {
                int idx = tid + e * 256;
                Bs[idx / BN][idx % BN] = bReg[e];
            }
        }
        __syncthreads();
    }
    float* pout = part + (size_t)blockIdx.y * 128 * N;
    #pragma unroll
    for (int ns = 0; ns < NSUB; ns++) {
        int col = n0 + ns * 8 + tig * 2;
        pout[row * N + col]           = c[ns][0];
        pout[row * N + col + 1]       = c[ns][1];
        pout[(row + 8) * N + col]     = c[ns][2];
        pout[(row + 8) * N + col + 1] = c[ns][3];
    }
}

__global__ void reduce_bias_relu_k(const float* __restrict__ part,
                                   const float* __restrict__ bias,
                                   float* __restrict__ out, int N, int ksplit) {
    int idx = blockIdx.x * 256 + threadIdx.x;
    if (idx >= 128 * N) return;
    int n = idx % N;
    float s = bias[n];
    for (int k = 0; k < ksplit; k++) s += part[k * 128 * N + idx];
    out[idx] = fmaxf(s, 0.f);
}

// ---------------- layer-3 reduce + classifier head + output pack (fused) ----------------
__global__ void head3_k(const float* __restrict__ b3,
                        const float* __restrict__ wc, const float* __restrict__ bc,
                        float* __restrict__ out, int out_size) {
    int s = threadIdx.x;   // 128 segments
    float l0 = bc[0], l1 = bc[1];
    #pragma unroll
    for (int j = 0; j < D_LOW; j++) {
        float a = b3[j];
        #pragma unroll
        for (int k = 0; k < KSPLIT2; k++) a += g_part[k * 128 * D_LOW + s * D_LOW + j];
        float h = fmaxf(a, 0.f);
        l0 += h * wc[j * 2 + 0];
        l1 += h * wc[j * 2 + 1];
    }
    float m = fmaxf(l0, l1);
    float e0 = expf(l0 - m), e1 = expf(l1 - m);
    float inv = 1.f / (e0 + e1);
    out[2 * s]     = e0 * inv;
    out[2 * s + 1] = e1 * inv;
    if (out_size >= 384) out[256 + s] = (float)g_lab2[s];
}

// ---------------- launch ----------------
extern "C" void kernel_launch(void* const* d_in, const int* in_sizes, int n_in,
                              void* d_out, int out_size) {
    const float* pixfeat = (const float*)d_in[0];
    const float* w1 = (const float*)d_in[1];
    const float* b1 = (const float*)d_in[2];
    const float* w2 = (const float*)d_in[3];
    const float* b2 = (const float*)d_in[4];
    const float* w3 = (const float*)d_in[5];
    const float* b3 = (const float*)d_in[6];
    const float* wc = (const float*)d_in[7];
    const float* bc = (const float*)d_in[8];
    const int*   sp = (const int*)d_in[9];
    const int*   yy = (const int*)d_in[10];
    float* out = (float*)d_out;

    float *p_feat, *p_h1, *p_h2, *p_part;
    cudaGetSymbolAddress((void**)&p_feat, g_feat);
    cudaGetSymbolAddress((void**)&p_h1,   g_h1);
    cudaGetSymbolAddress((void**)&p_h2,   g_h2);
    cudaGetSymbolAddress((void**)&p_part, g_part);

    cudaStream_t sB;
    cudaStreamCreateWithFlags(&sB, cudaStreamNonBlocking);
    cudaEvent_t eA, eB;
    cudaEventCreateWithFlags(&eA, cudaEventDisableTiming);
    cudaEventCreateWithFlags(&eB, cudaEventDisableTiming);

    hist_k<<<NBLK, 256>>>(sp, yy);
    scan_k<<<1, 128>>>();
    scatter_k<<<NBLK, 256>>>(sp);
    segsum_k<<<dim3(NCB, NSEG), 128>>>(pixfeat);

    // fork: affinity/label propagation runs concurrently with the MLP chain
    cudaEventRecord(eA, 0);
    cudaStreamWaitEvent(sB, eA, 0);
    aff_k<<<64, 128, 0, sB>>>();
    cudaEventRecord(eB, sB);

    // MLP chain on main stream
    gemm_tf32_k<8><<<dim3(D_HID / 64, KSPLIT1), 256>>>(p_feat, w1, p_part, D_HID, C_FEAT, C_FEAT / 8 / KSPLIT1);
    reduce_bias_relu_k<<<(128 * D_HID + 255) / 256, 256>>>(p_part, b1, p_h1, D_HID, KSPLIT1);
    gemm_tf32_k<8><<<dim3(D_HID / 64, KSPLIT2), 256>>>(p_h1, w2, p_part, D_HID, D_HID, D_HID / 8 / KSPLIT2);
    reduce_bias_relu_k<<<(128 * D_HID + 255) / 256, 256>>>(p_part, b2, p_h2, D_HID, KSPLIT2);
    gemm_tf32_k<4><<<dim3(1, KSPLIT2), 256>>>(p_h2, w3, p_part, D_LOW, D_HID, D_HID / 8 / KSPLIT2);

    cudaStreamWaitEvent((cudaStream_t)0, eB, 0);
    head3_k<<<1, 128>>>(b3, wc, bc, out, out_size);
}

// round 6
// speedup vs baseline: 1.0827x; 1.0827x over previous
#include <cuda_runtime.h>
#include <cstdint>
#include <math.h>

#define N_PIX  50176
#define C_FEAT 4224
#define C4     1056      // C_FEAT/4
#define NSEG   128
#define D_HID  1024
#define D_LOW  32
#define KSPLIT1 16
#define KSPLIT2 8
#define NBLK   196       // N_PIX / 256
#define NCB    33        // C_FEAT / 128

// ---------------- scratch (static device globals; all fully overwritten each call) ----------------
__device__ int   g_blockhist[NBLK * NSEG];
__device__ int   g_blockcls[NBLK * NSEG * 3];
__device__ int   g_blockbase[NBLK * NSEG];
__device__ int   g_counts[NSEG];
__device__ int   g_start[NSEG];
__device__ int   g_perm[N_PIX];
__device__ float g_feat[NSEG * C_FEAT];
__device__ float g_norm2p[NSEG * NCB];
__device__ int   g_lab[NSEG];
__device__ int   g_labeled[NSEG];
__device__ int   g_lab2[NSEG];
__device__ float g_part[KSPLIT1 * 128 * 1024];
__device__ float g_h1[128 * D_HID];
__device__ float g_h2[128 * D_HID];

// ---------------- per-block histogram (no global atomics, no pre-zero) ----------------
__global__ void hist_k(const int* __restrict__ sp, const int* __restrict__ y) {
    __shared__ int hc[NSEG];
    __shared__ int hcls[NSEG * 3];
    int t = threadIdx.x;
    int b = blockIdx.x;
    if (t < NSEG) hc[t] = 0;
    for (int i = t; i < NSEG * 3; i += 256) hcls[i] = 0;
    __syncthreads();
    int i = b * 256 + t;
    int s = sp[i];
    atomicAdd(&hc[s], 1);
    atomicAdd(&hcls[s * 3 + y[i]], 1);
    __syncthreads();
    if (t < NSEG) g_blockhist[b * NSEG + t] = hc[t];
    for (int i2 = t; i2 < NSEG * 3; i2 += 256) g_blockcls[b * NSEG * 3 + i2] = hcls[i2];
}

// ---------------- scan over block hists + labels ----------------
__global__ void scan_k() {
    __shared__ int sh[NSEG];
    int t = threadIdx.x;   // = segment
    int tot = 0;
    #pragma unroll 4
    for (int b = 0; b < NBLK; b++) tot += g_blockhist[b * NSEG + t];
    sh[t] = tot;
    __syncthreads();
    if (t == 0) {
        int acc = 0;
        for (int i = 0; i < NSEG; i++) { int c = sh[i]; sh[i] = acc; acc += c; }
    }
    __syncthreads();
    int startv = sh[t];
    g_counts[t] = tot;
    g_start[t] = startv;
    int run = startv;
    #pragma unroll 4
    for (int b = 0; b < NBLK; b++) {
        g_blockbase[b * NSEG + t] = run;
        run += g_blockhist[b * NSEG + t];
    }
    int c0 = 0, c1 = 0, c2 = 0;
    #pragma unroll 4
    for (int b = 0; b < NBLK; b++) {
        const int* p = &g_blockcls[b * NSEG * 3 + t * 3];
        c0 += p[0]; c1 += p[1]; c2 += p[2];
    }
    int l = 0, best = c0;
    if (c1 > best) { best = c1; l = 1; }
    if (c2 > best) { best = c2; l = 2; }
    int fb = (c2 > (tot >> 1)) ? 2 : ((c1 >= 1) ? 1 : 0);
    if (l == 0) l = fb;
    g_lab[t] = l;
    g_labeled[t] = (l != 0);
}

// ---------------- scatter pixels into per-segment contiguous ranges ----------------
__global__ void scatter_k(const int* __restrict__ sp) {
    __shared__ int hc[NSEG];
    int t = threadIdx.x;
    int b = blockIdx.x;
    if (t < NSEG) hc[t] = 0;
    __syncthreads();
    int i = b * 256 + t;
    int s = sp[i];
    int r = atomicAdd(&hc[s], 1);
    g_perm[g_blockbase[b * NSEG + s] + r] = i;
}

// ---------------- segment sum: grid (33 col-chunks, 128 segments), 128 thr ----------------
__global__ void __launch_bounds__(128) segsum_k(const float* __restrict__ pixfeat) {
    __shared__ int   rows[512];
    __shared__ float red[4][128];
    int tid = threadIdx.x;
    int ty = tid >> 5, lane = tid & 31;
    int s = blockIdx.y;
    int cb = blockIdx.x * 128;
    int st = g_start[s], cnt = g_counts[s];
    const float4* pf = (const float4*)pixfeat;
    int cb4 = cb >> 2;
    float4 acc = make_float4(0.f, 0.f, 0.f, 0.f);

    for (int c0 = 0; c0 < cnt; c0 += 512) {
        int clim = min(512, cnt - c0);
        __syncthreads();
        for (int i = tid; i < clim; i += 128) rows[i] = g_perm[st + c0 + i];
        __syncthreads();
        int main_end = clim & ~31;
        for (int g = 0; g < main_end; g += 32) {
            int base = g + ty * 8;
            float4 v[8];
            #pragma unroll
            for (int u = 0; u < 8; u++)
                v[u] = __ldcs(&pf[(size_t)rows[base + u] * C4 + cb4 + lane]);
            #pragma unroll
            for (int u = 0; u < 8; u++) {
                acc.x += v[u].x; acc.y += v[u].y; acc.z += v[u].z; acc.w += v[u].w;
            }
        }
        for (int j = main_end + ty; j < clim; j += 4) {
            float4 v = __ldcs(&pf[(size_t)rows[j] * C4 + cb4 + lane]);
            acc.x += v.x; acc.y += v.y; acc.z += v.z; acc.w += v.w;
        }
    }
    __syncthreads();
    red[ty][lane * 4 + 0] = acc.x;
    red[ty][lane * 4 + 1] = acc.y;
    red[ty][lane * 4 + 2] = acc.z;
    red[ty][lane * 4 + 3] = acc.w;
    __syncthreads();
    float sum = red[0][tid] + red[1][tid] + red[2][tid] + red[3][tid];
    float inv = 1.f / fmaxf((float)cnt, 1.f);
    float f = sum * inv;
    g_feat[s * C_FEAT + cb + tid] = f;
    __syncthreads();
    red[0][tid] = f * f;
    __syncthreads();
    for (int s2 = 64; s2 > 0; s2 >>= 1) {
        if (tid < s2) red[0][tid] += red[0][tid + s2];
        __syncthreads();
    }
    if (tid == 0) g_norm2p[s * NCB + blockIdx.x] = red[0][0];
}

// ---------------- affinity + label propagation: grid 64 blocks, rows {b, b+64} ----------------
__global__ void __launch_bounds__(128) aff_k() {
    __shared__ float4 a0s4[16], a1s4[16];
    __shared__ float4 bs4[128][17];
    __shared__ float  rn[128];
    __shared__ float  rv0[128], rv1[128];
    __shared__ int    ri0[128], ri1[128];
    int tid = threadIdx.x;
    int i0 = blockIdx.x, i1 = blockIdx.x + 64;

    {
        float n2 = 0.f;
        #pragma unroll
        for (int i = 0; i < NCB; i++) n2 += g_norm2p[tid * NCB + i];
        rn[tid] = rsqrtf(n2);
    }

    const float4* feat4 = (const float4*)g_feat;
    float acc0 = 0.f, acc1 = 0.f;

    for (int k0 = 0; k0 < C4; k0 += 16) {
        __syncthreads();
        if (tid < 16)       a0s4[tid]      = feat4[i0 * C4 + k0 + tid];
        else if (tid < 32)  a1s4[tid - 16] = feat4[i1 * C4 + k0 + (tid - 16)];
        #pragma unroll
        for (int i = 0; i < 16; i++) {
            int idx = tid + i * 128;
            int r = idx >> 4, c = idx & 15;
            bs4[r][c] = feat4[r * C4 + k0 + c];
        }
        __syncthreads();
        #pragma unroll
        for (int kk = 0; kk < 16; kk++) {
            float4 bv = bs4[tid][kk];
            float4 x = a0s4[kk];
            float4 yv = a1s4[kk];
            acc0 += x.x * bv.x + x.y * bv.y + x.z * bv.z + x.w * bv.w;
            acc1 += yv.x * bv.x + yv.y * bv.y + yv.z * bv.z + yv.w * bv.w;
        }
    }
    float rj = rn[tid];
    bool labj = (g_labeled[tid] != 0);
    float v0 = labj ? acc0 * rn[i0] * rj : -INFINITY;
    float v1 = labj ? acc1 * rn[i1] * rj : -INFINITY;

    rv0[tid] = v0; ri0[tid] = tid;
    rv1[tid] = v1; ri1[tid] = tid;
    __syncthreads();
    for (int s2 = 64; s2 > 0; s2 >>= 1) {
        if (tid < s2) {
            float a = rv0[tid + s2]; int ia = ri0[tid + s2];
            if (a > rv0[tid] || (a == rv0[tid] && ia < ri0[tid])) { rv0[tid] = a; ri0[tid] = ia; }
            float b = rv1[tid + s2]; int ib = ri1[tid + s2];
            if (b > rv1[tid] || (b == rv1[tid] && ib < ri1[tid])) { rv1[tid] = b; ri1[tid] = ib; }
        }
        __syncthreads();
    }
    if (tid == 0) {
        g_lab2[i0] = (!g_labeled[i0] && rv0[0] > 0.8f) ? g_lab[ri0[0]] : g_lab[i0];
        g_lab2[i1] = (!g_labeled[i1] && rv1[0] > 0.8f) ? g_lab[ri1[0]] : g_lab[i1];
    }
}

// ---------------- tf32 MMA GEMM (M=128), split-K partials, chunked smem + reg double-buffer ----------------
// fp32 bits fed directly to tf32 mma (truncation; error ~2^-10 rel, fine at 1e-3 tol)
__device__ __forceinline__ void mma8(float& c0, float& c1, float& c2, float& c3,
                                     unsigned a0, unsigned a1, unsigned a2, unsigned a3,
                                     unsigned b0, unsigned b1) {
    asm volatile(
        "mma.sync.aligned.m16n8k8.row.col.f32.tf32.tf32.f32 "
        "{%0,%1,%2,%3},{%4,%5,%6,%7},{%8,%9},{%0,%1,%2,%3};\n"
        : "+f"(c0), "+f"(c1), "+f"(c2), "+f"(c3)
        : "r"(a0), "r"(a1), "r"(a2), "r"(a3), "r"(b0), "r"(b1));
}

// NSUB: N columns / 8 handled per block. CH: mma k-steps per smem chunk. NCH: chunks per block.
template<int NSUB, int CH, int NCH>
__global__ void __launch_bounds__(256) gemm_tf32_k(const float* __restrict__ A,
                                                   const float* __restrict__ B,
                                                   float* __restrict__ part,
                                                   int N, int K) {
    const int BN = 8 * NSUB;
    const int KC = CH * 8;            // K width of one chunk
    const int CW = KC / 4;            // float4 per A row
    const int BE = (KC * BN) / 256;   // B elements per thread
    __shared__ unsigned As[128][KC + 1];
    __shared__ unsigned Bs[KC][BN + 4];
    int tid = threadIdx.x;
    int warp = tid >> 5, lane = tid & 31;
    int grp = lane >> 2, tig = lane & 3;
    int n0 = blockIdx.x * BN;
    int k_begin = blockIdx.y * (KC * NCH);

    float c[NSUB][4];
    #pragma unroll
    for (int i = 0; i < NSUB; i++) { c[i][0] = c[i][1] = c[i][2] = c[i][3] = 0.f; }

    uint4    aPre[CH];
    unsigned bPre[BE];

    // preload chunk 0 into registers
    #pragma unroll
    for (int e = 0; e < CH; e++) {
        int idx = tid + e * 256;          // float4 index in 128 x CW space
        int r = idx / CW, c4 = idx % CW;
        aPre[e] = *(const uint4*)(A + (size_t)r * K + k_begin + c4 * 4);
    }
    #pragma unroll
    for (int e = 0; e < BE; e++) {
        int idx = tid + e * 256;
        int kr = idx / BN, n = idx % BN;
        bPre[e] = __float_as_uint(B[(size_t)(k_begin + kr) * N + n0 + n]);
    }
    // store chunk 0
    #pragma unroll
    for (int e = 0; e < CH; e++) {
        int idx = tid + e * 256;
        int r = idx / CW, c4 = idx % CW;
        As[r][c4 * 4 + 0] = aPre[e].x; As[r][c4 * 4 + 1] = aPre[e].y;
        As[r][c4 * 4 + 2] = aPre[e].z; As[r][c4 * 4 + 3] = aPre[e].w;
    }
    #pragma unroll
    for (int e = 0; e < BE; e++) {
        int idx = tid + e * 256;
        Bs[idx / BN][idx % BN] = bPre[e];
    }
    __syncthreads();

    int row = 16 * warp + grp;
    #pragma unroll 1
    for (int ch = 0; ch < NCH; ch++) {
        // prefetch next chunk into registers
        if (ch + 1 < NCH) {
            int kk = k_begin + (ch + 1) * KC;
            #pragma unroll
            for (int e = 0; e < CH; e++) {
                int idx = tid + e * 256;
                int r = idx / CW, c4 = idx % CW;
                aPre[e] = *(const uint4*)(A + (size_t)r * K + kk + c4 * 4);
            }
            #pragma unroll
            for (int e = 0; e < BE; e++) {
                int idx = tid + e * 256;
                int kr = idx / BN, n = idx % BN;
                bPre[e] = __float_as_uint(B[(size_t)(kk + kr) * N + n0 + n]);
            }
        }
        // compute CH k-steps from smem
        #pragma unroll
        for (int m = 0; m < CH; m++) {
            int k0 = m * 8;
            unsigned a0 = As[row][k0 + tig];
            unsigned a1 = As[row + 8][k0 + tig];
            unsigned a2 = As[row][k0 + tig + 4];
            unsigned a3 = As[row + 8][k0 + tig + 4];
            #pragma unroll
            for (int ns = 0; ns < NSUB; ns++) {
                unsigned b0 = Bs[k0 + tig][ns * 8 + grp];
                unsigned b1 = Bs[k0 + tig + 4][ns * 8 + grp];
                mma8(c[ns][0], c[ns][1], c[ns][2], c[ns][3], a0, a1, a2, a3, b0, b1);
            }
        }
        __syncthreads();
        if (ch + 1 < NCH) {
            #pragma unroll
            for (int e = 0; e < CH; e++) {
                int idx = tid + e * 256;
                int r = idx / CW, c4 = idx % CW;
                As[r][c4 * 4 + 0] = aPre[e].x; As[r][c4 * 4 + 1] = aPre[e].y;
                As[r][c4 * 4 + 2] = aPre[e].z; As[r][c4 * 4 + 3] = aPre[e].w;
            }
            #pragma unroll
            for (int e = 0; e < BE; e++) {
                int idx = tid + e * 256;
                Bs[idx / BN][idx % BN] = bPre[e];
            }
            __syncthreads();
        }
    }
    float* pout = part + (size_t)blockIdx.y * 128 * N;
    #pragma unroll
    for (int ns = 0; ns < NSUB; ns++) {
        int col = n0 + ns * 8 + tig * 2;
        pout[row * N + col]           = c[ns][0];
        pout[row * N + col + 1]       = c[ns][1];
        pout[(row + 8) * N + col]     = c[ns][2];
        pout[(row + 8) * N + col + 1] = c[ns][3];
    }
}

__global__ void reduce_bias_relu_k(const float* __restrict__ part,
                                   const float* __restrict__ bias,
                                   float* __restrict__ out, int N, int ksplit) {
    int idx = blockIdx.x * 256 + threadIdx.x;
    if (idx >= 128 * N) return;
    int n = idx % N;
    float s = bias[n];
    for (int k = 0; k < ksplit; k++) s += part[k * 128 * N + idx];
    out[idx] = fmaxf(s, 0.f);
}

// ---------------- layer-3 reduce + classifier head + output pack (fused) ----------------
__global__ void head3_k(const float* __restrict__ b3,
                        const float* __restrict__ wc, const float* __restrict__ bc,
                        float* __restrict__ out, int out_size) {
    int s = threadIdx.x;   // 128 segments
    float l0 = bc[0], l1 = bc[1];
    #pragma unroll
    for (int j = 0; j < D_LOW; j++) {
        float a = b3[j];
        #pragma unroll
        for (int k = 0; k < KSPLIT2; k++) a += g_part[k * 128 * D_LOW + s * D_LOW + j];
        float h = fmaxf(a, 0.f);
        l0 += h * wc[j * 2 + 0];
        l1 += h * wc[j * 2 + 1];
    }
    float m = fmaxf(l0, l1);
    float e0 = expf(l0 - m), e1 = expf(l1 - m);
    float inv = 1.f / (e0 + e1);
    out[2 * s]     = e0 * inv;
    out[2 * s + 1] = e1 * inv;
    if (out_size >= 384) out[256 + s] = (float)g_lab2[s];
}

// ---------------- launch ----------------
extern "C" void kernel_launch(void* const* d_in, const int* in_sizes, int n_in,
                              void* d_out, int out_size) {
    const float* pixfeat = (const float*)d_in[0];
    const float* w1 = (const float*)d_in[1];
    const float* b1 = (const float*)d_in[2];
    const float* w2 = (const float*)d_in[3];
    const float* b2 = (const float*)d_in[4];
    const float* w3 = (const float*)d_in[5];
    const float* b3 = (const float*)d_in[6];
    const float* wc = (const float*)d_in[7];
    const float* bc = (const float*)d_in[8];
    const int*   sp = (const int*)d_in[9];
    const int*   yy = (const int*)d_in[10];
    float* out = (float*)d_out;

    float *p_feat, *p_h1, *p_h2, *p_part;
    cudaGetSymbolAddress((void**)&p_feat, g_feat);
    cudaGetSymbolAddress((void**)&p_h1,   g_h1);
    cudaGetSymbolAddress((void**)&p_h2,   g_h2);
    cudaGetSymbolAddress((void**)&p_part, g_part);

    cudaStream_t sB;
    cudaStreamCreateWithFlags(&sB, cudaStreamNonBlocking);
    cudaEvent_t eA, eB;
    cudaEventCreateWithFlags(&eA, cudaEventDisableTiming);
    cudaEventCreateWithFlags(&eB, cudaEventDisableTiming);

    hist_k<<<NBLK, 256>>>(sp, yy);
    scan_k<<<1, 128>>>();
    scatter_k<<<NBLK, 256>>>(sp);
    segsum_k<<<dim3(NCB, NSEG), 128>>>(pixfeat);

    // fork: affinity/label propagation runs concurrently with the MLP chain
    cudaEventRecord(eA, 0);
    cudaStreamWaitEvent(sB, eA, 0);
    aff_k<<<64, 128, 0, sB>>>();
    cudaEventRecord(eB, sB);

    // MLP chain on main stream
    // GEMM1: K=4224 = KSPLIT1(16) * CH(3)*8 * NCH(11)
    gemm_tf32_k<8, 3, 11><<<dim3(D_HID / 64, KSPLIT1), 256>>>(p_feat, w1, p_part, D_HID, C_FEAT);
    reduce_bias_relu_k<<<(128 * D_HID + 255) / 256, 256>>>(p_part, b1, p_h1, D_HID, KSPLIT1);
    // GEMM2: K=1024 = KSPLIT2(8) * CH(4)*8 * NCH(4)
    gemm_tf32_k<8, 4, 4><<<dim3(D_HID / 64, KSPLIT2), 256>>>(p_h1, w2, p_part, D_HID, D_HID);
    reduce_bias_relu_k<<<(128 * D_HID + 255) / 256, 256>>>(p_part, b2, p_h2, D_HID, KSPLIT2);
    // GEMM3: N=32
    gemm_tf32_k<4, 4, 4><<<dim3(1, KSPLIT2), 256>>>(p_h2, w3, p_part, D_LOW, D_HID);

    cudaStreamWaitEvent((cudaStream_t)0, eB, 0);
    head3_k<<<1, 128>>>(b3, wc, bc, out, out_size);
}

// round 7
// speedup vs baseline: 1.0919x; 1.0085x over previous
#include <cuda_runtime.h>
#include <cstdint>
#include <math.h>

#define N_PIX  50176
#define C_FEAT 4224
#define C4     1056      // C_FEAT/4
#define NSEG   128
#define D_HID  1024
#define D_LOW  32
#define KSPLIT1 16
#define KSPLIT2 8
#define NBLK   196       // N_PIX / 256
#define NCB    33        // C_FEAT / 128

// ---------------- scratch (static device globals; zero-init on load, reset by head3) ----------------
__device__ int   g_blockhist[NBLK * NSEG];
__device__ int   g_blockbase[NBLK * NSEG];
__device__ int   g_cls[NSEG * 3];       // global atomic class counts (reset each run)
__device__ int   g_bar1;                // arrival counter (reset each run)
__device__ int   g_flag1;               // scan-done flag (reset each run)
__device__ int   g_counts[NSEG];
__device__ int   g_start[NSEG];
__device__ int   g_perm[N_PIX];
__device__ float g_feat[NSEG * C_FEAT];
__device__ float g_norm2p[NSEG * NCB];
__device__ int   g_lab[NSEG];
__device__ int   g_labeled[NSEG];
__device__ int   g_lab2[NSEG];
__device__ float g_part[KSPLIT1 * 128 * 1024];
__device__ float g_part3[KSPLIT2 * 128 * D_LOW];
__device__ float g_h1[128 * D_HID];

// ---------------- fused prep: hist + scan + labels + scatter (single kernel) ----------------
__global__ void __launch_bounds__(256) prep_k(const int* __restrict__ sp,
                                              const int* __restrict__ y) {
    __shared__ int hc[NSEG];
    __shared__ int hcls[NSEG * 3];
    __shared__ int hcur[NSEG];
    __shared__ int h0s[NSEG], h1s[NSEG], startv[NSEG];
    __shared__ bool lastblk;
    int t = threadIdx.x;
    int b = blockIdx.x;

    // ---- phase A: per-block histogram ----
    if (t < NSEG) hc[t] = 0;
    for (int j = t; j < NSEG * 3; j += 256) hcls[j] = 0;
    __syncthreads();
    int i = b * 256 + t;
    int s = sp[i];
    atomicAdd(&hc[s], 1);
    atomicAdd(&hcls[s * 3 + y[i]], 1);
    __syncthreads();
    if (t < NSEG) g_blockhist[b * NSEG + t] = hc[t];
    for (int j = t; j < NSEG * 3; j += 256)
        if (hcls[j]) atomicAdd(&g_cls[j], hcls[j]);
    __threadfence();
    __syncthreads();
    if (t == 0) {
        int a = atomicAdd(&g_bar1, 1);
        lastblk = (a == NBLK - 1);
    }
    __syncthreads();

    // ---- phase B: last-arriving block performs the scan ----
    if (lastblk) {
        __threadfence();
        int s2 = t & 127;
        int half = t >> 7;            // 0 or 1
        int b0 = half * 98, b1 = b0 + 98;
        int sum = 0;
        #pragma unroll 7
        for (int bb = b0; bb < b1; bb++) sum += g_blockhist[bb * NSEG + s2];
        if (half == 0) h0s[s2] = sum; else h1s[s2] = sum;
        __syncthreads();
        if (t == 0) {
            int acc = 0;
            for (int ss = 0; ss < NSEG; ss++) {
                startv[ss] = acc;
                acc += h0s[ss] + h1s[ss];
            }
        }
        __syncthreads();
        if (t < NSEG) {
            int tot = h0s[t] + h1s[t];
            g_counts[t] = tot;
            g_start[t] = startv[t];
            int c0 = g_cls[t * 3], c1 = g_cls[t * 3 + 1], c2 = g_cls[t * 3 + 2];
            int l = 0, best = c0;
            if (c1 > best) { best = c1; l = 1; }
            if (c2 > best) { best = c2; l = 2; }
            int fb = (c2 > (tot >> 1)) ? 2 : ((c1 >= 1) ? 1 : 0);
            if (l == 0) l = fb;
            g_lab[t] = l;
            g_labeled[t] = (l != 0);
        }
        int run = startv[s2] + (half ? h0s[s2] : 0);
        for (int bb = b0; bb < b1; bb++) {
            g_blockbase[bb * NSEG + s2] = run;
            run += g_blockhist[bb * NSEG + s2];
        }
        __threadfence();
        __syncthreads();
        if (t == 0) atomicExch(&g_flag1, 1);
    }

    // ---- wait for scan done ----
    if (t == 0) {
        while (atomicAdd(&g_flag1, 0) == 0) __nanosleep(200);
    }
    __syncthreads();
    __threadfence();

    // ---- phase C: scatter ----
    if (t < NSEG) hcur[t] = 0;
    __syncthreads();
    int r = atomicAdd(&hcur[s], 1);
    g_perm[g_blockbase[b * NSEG + s] + r] = i;
}

// ---------------- segment sum: grid (33 col-chunks, 128 segments), 128 thr ----------------
__global__ void __launch_bounds__(128) segsum_k(const float* __restrict__ pixfeat) {
    __shared__ int   rows[512];
    __shared__ float red[4][128];
    int tid = threadIdx.x;
    int ty = tid >> 5, lane = tid & 31;
    int s = blockIdx.y;
    int cb = blockIdx.x * 128;
    int st = g_start[s], cnt = g_counts[s];
    const float4* pf = (const float4*)pixfeat;
    int cb4 = cb >> 2;
    float4 acc = make_float4(0.f, 0.f, 0.f, 0.f);

    for (int c0 = 0; c0 < cnt; c0 += 512) {
        int clim = min(512, cnt - c0);
        __syncthreads();
        for (int i = tid; i < clim; i += 128) rows[i] = g_perm[st + c0 + i];
        __syncthreads();
        int main_end = clim & ~31;
        for (int g = 0; g < main_end; g += 32) {
            int base = g + ty * 8;
            float4 v[8];
            #pragma unroll
            for (int u = 0; u < 8; u++)
                v[u] = __ldcs(&pf[(size_t)rows[base + u] * C4 + cb4 + lane]);
            #pragma unroll
            for (int u = 0; u < 8; u++) {
                acc.x += v[u].x; acc.y += v[u].y; acc.z += v[u].z; acc.w += v[u].w;
            }
        }
        for (int j = main_end + ty; j < clim; j += 4) {
            float4 v = __ldcs(&pf[(size_t)rows[j] * C4 + cb4 + lane]);
            acc.x += v.x; acc.y += v.y; acc.z += v.z; acc.w += v.w;
        }
    }
    __syncthreads();
    red[ty][lane * 4 + 0] = acc.x;
    red[ty][lane * 4 + 1] = acc.y;
    red[ty][lane * 4 + 2] = acc.z;
    red[ty][lane * 4 + 3] = acc.w;
    __syncthreads();
    float sum = red[0][tid] + red[1][tid] + red[2][tid] + red[3][tid];
    float inv = 1.f / fmaxf((float)cnt, 1.f);
    float f = sum * inv;
    g_feat[s * C_FEAT + cb + tid] = f;
    __syncthreads();
    red[0][tid] = f * f;
    __syncthreads();
    for (int s2 = 64; s2 > 0; s2 >>= 1) {
        if (tid < s2) red[0][tid] += red[0][tid + s2];
        __syncthreads();
    }
    if (tid == 0) g_norm2p[s * NCB + blockIdx.x] = red[0][0];
}

// ---------------- affinity + label propagation: grid 64 blocks, rows {b, b+64} ----------------
__global__ void __launch_bounds__(128) aff_k() {
    __shared__ float4 a0s4[16], a1s4[16];
    __shared__ float4 bs4[128][17];
    __shared__ float  rn[128];
    __shared__ float  rv0[128], rv1[128];
    __shared__ int    ri0[128], ri1[128];
    int tid = threadIdx.x;
    int i0 = blockIdx.x, i1 = blockIdx.x + 64;

    {
        float n2 = 0.f;
        #pragma unroll
        for (int i = 0; i < NCB; i++) n2 += g_norm2p[tid * NCB + i];
        rn[tid] = rsqrtf(n2);
    }

    const float4* feat4 = (const float4*)g_feat;
    float acc0 = 0.f, acc1 = 0.f;

    for (int k0 = 0; k0 < C4; k0 += 16) {
        __syncthreads();
        if (tid < 16)       a0s4[tid]      = feat4[i0 * C4 + k0 + tid];
        else if (tid < 32)  a1s4[tid - 16] = feat4[i1 * C4 + k0 + (tid - 16)];
        #pragma unroll
        for (int i = 0; i < 16; i++) {
            int idx = tid + i * 128;
            int r = idx >> 4, c = idx & 15;
            bs4[r][c] = feat4[r * C4 + k0 + c];
        }
        __syncthreads();
        #pragma unroll
        for (int kk = 0; kk < 16; kk++) {
            float4 bv = bs4[tid][kk];
            float4 x = a0s4[kk];
            float4 yv = a1s4[kk];
            acc0 += x.x * bv.x + x.y * bv.y + x.z * bv.z + x.w * bv.w;
            acc1 += yv.x * bv.x + yv.y * bv.y + yv.z * bv.z + yv.w * bv.w;
        }
    }
    float rj = rn[tid];
    bool labj = (g_labeled[tid] != 0);
    float v0 = labj ? acc0 * rn[i0] * rj : -INFINITY;
    float v1 = labj ? acc1 * rn[i1] * rj : -INFINITY;

    rv0[tid] = v0; ri0[tid] = tid;
    rv1[tid] = v1; ri1[tid] = tid;
    __syncthreads();
    for (int s2 = 64; s2 > 0; s2 >>= 1) {
        if (tid < s2) {
            float a = rv0[tid + s2]; int ia = ri0[tid + s2];
            if (a > rv0[tid] || (a == rv0[tid] && ia < ri0[tid])) { rv0[tid] = a; ri0[tid] = ia; }
            float b = rv1[tid + s2]; int ib = ri1[tid + s2];
            if (b > rv1[tid] || (b == rv1[tid] && ib < ri1[tid])) { rv1[tid] = b; ri1[tid] = ib; }
        }
        __syncthreads();
    }
    if (tid == 0) {
        g_lab2[i0] = (!g_labeled[i0] && rv0[0] > 0.8f) ? g_lab[ri0[0]] : g_lab[i0];
        g_lab2[i1] = (!g_labeled[i1] && rv1[0] > 0.8f) ? g_lab[ri1[0]] : g_lab[i1];
    }
}

// ---------------- tf32 MMA GEMM (M=128), split-K partials, chunked smem + reg double-buffer ----------------
__device__ __forceinline__ void mma8(float& c0, float& c1, float& c2, float& c3,
                                     unsigned a0, unsigned a1, unsigned a2, unsigned a3,
                                     unsigned b0, unsigned b1) {
    asm volatile(
        "mma.sync.aligned.m16n8k8.row.col.f32.tf32.tf32.f32 "
        "{%0,%1,%2,%3},{%4,%5,%6,%7},{%8,%9},{%0,%1,%2,%3};\n"
        : "+f"(c0), "+f"(c1), "+f"(c2), "+f"(c3)
        : "r"(a0), "r"(a1), "r"(a2), "r"(a3), "r"(b0), "r"(b1));
}

template<int NSUB, int CH, int NCH>
__global__ void __launch_bounds__(256) gemm_tf32_k(const float* __restrict__ A,
                                                   const float* __restrict__ B,
                                                   float* __restrict__ part,
                                                   int N, int K) {
    const int BN = 8 * NSUB;
    const int KC = CH * 8;
    const int CW = KC / 4;
    const int BE = (KC * BN) / 256;
    __shared__ unsigned As[128][KC + 1];
    __shared__ unsigned Bs[KC][BN + 4];
    int tid = threadIdx.x;
    int warp = tid >> 5, lane = tid & 31;
    int grp = lane >> 2, tig = lane & 3;
    int n0 = blockIdx.x * BN;
    int k_begin = blockIdx.y * (KC * NCH);

    float c[NSUB][4];
    #pragma unroll
    for (int i = 0; i < NSUB; i++) { c[i][0] = c[i][1] = c[i][2] = c[i][3] = 0.f; }

    uint4    aPre[CH];
    unsigned bPre[BE];

    #pragma unroll
    for (int e = 0; e < CH; e++) {
        int idx = tid + e * 256;
        int r = idx / CW, c4 = idx % CW;
        aPre[e] = *(const uint4*)(A + (size_t)r * K + k_begin + c4 * 4);
    }
    #pragma unroll
    for (int e = 0; e < BE; e++) {
        int idx = tid + e * 256;
        int kr = idx / BN, n = idx % BN;
        bPre[e] = __float_as_uint(B[(size_t)(k_begin + kr) * N + n0 + n]);
    }
    #pragma unroll
    for (int e = 0; e < CH; e++) {
        int idx = tid + e * 256;
        int r = idx / CW, c4 = idx % CW;
        As[r][c4 * 4 + 0] = aPre[e].x; As[r][c4 * 4 + 1] = aPre[e].y;
        As[r][c4 * 4 + 2] = aPre[e].z; As[r][c4 * 4 + 3] = aPre[e].w;
    }
    #pragma unroll
    for (int e = 0; e < BE; e++) {
        int idx = tid + e * 256;
        Bs[idx / BN][idx % BN] = bPre[e];
    }
    __syncthreads();

    int row = 16 * warp + grp;
    #pragma unroll 1
    for (int ch = 0; ch < NCH; ch++) {
        if (ch + 1 < NCH) {
            int kk = k_begin + (ch + 1) * KC;
            #pragma unroll
            for (int e = 0; e < CH; e++) {
                int idx = tid + e * 256;
                int r = idx / CW, c4 = idx % CW;
                aPre[e] = *(const uint4*)(A + (size_t)r * K + kk + c4 * 4);
            }
            #pragma unroll
            for (int e = 0; e < BE; e++) {
                int idx = tid + e * 256;
                int kr = idx / BN, n = idx % BN;
                bPre[e] = __float_as_uint(B[(size_t)(kk + kr) * N + n0 + n]);
            }
        }
        #pragma unroll
        for (int m = 0; m < CH; m++) {
            int k0 = m * 8;
            unsigned a0 = As[row][k0 + tig];
            unsigned a1 = As[row + 8][k0 + tig];
            unsigned a2 = As[row][k0 + tig + 4];
            unsigned a3 = As[row + 8][k0 + tig + 4];
            #pragma unroll
            for (int ns = 0; ns < NSUB; ns++) {
                unsigned b0 = Bs[k0 + tig][ns * 8 + grp];
                unsigned b1 = Bs[k0 + tig + 4][ns * 8 + grp];
                mma8(c[ns][0], c[ns][1], c[ns][2], c[ns][3], a0, a1, a2, a3, b0, b1);
            }
        }
        __syncthreads();
        if (ch + 1 < NCH) {
            #pragma unroll
            for (int e = 0; e < CH; e++) {
                int idx = tid + e * 256;
                int r = idx / CW, c4 = idx % CW;
                As[r][c4 * 4 + 0] = aPre[e].x; As[r][c4 * 4 + 1] = aPre[e].y;
                As[r][c4 * 4 + 2] = aPre[e].z; As[r][c4 * 4 + 3] = aPre[e].w;
            }
            #pragma unroll
            for (int e = 0; e < BE; e++) {
                int idx = tid + e * 256;
                Bs[idx / BN][idx % BN] = bPre[e];
            }
            __syncthreads();
        }
    }
    float* pout = part + (size_t)blockIdx.y * 128 * N;
    #pragma unroll
    for (int ns = 0; ns < NSUB; ns++) {
        int col = n0 + ns * 8 + tig * 2;
        pout[row * N + col]           = c[ns][0];
        pout[row * N + col + 1]       = c[ns][1];
        pout[(row + 8) * N + col]     = c[ns][2];
        pout[(row + 8) * N + col + 1] = c[ns][3];
    }
}

// ---------------- GEMM3 fused with layer-2 reduce+bias+relu on A-load ----------------
// A(r,k) = relu(b2[k] + sum_p part2[p][r][k]);  B = w3 (K=1024 x N=32)
__global__ void __launch_bounds__(256) gemm3f_k(const float* __restrict__ part2,
                                                const float* __restrict__ b2,
                                                const float* __restrict__ B,
                                                float* __restrict__ part3) {
    const int NSUB = 4, CH = 4, NCH = 4;
    const int BN = 8 * NSUB;            // 32
    const int KC = CH * 8;              // 32
    const int CW = KC / 4;              // 8
    const int BE = (KC * BN) / 256;     // 4
    const int N = D_LOW, K = D_HID;
    __shared__ unsigned As[128][KC + 1];
    __shared__ unsigned Bs[KC][BN + 4];
    int tid = threadIdx.x;
    int warp = tid >> 5, lane = tid & 31;
    int grp = lane >> 2, tig = lane & 3;
    int k_begin = blockIdx.y * (KC * NCH);

    float c[NSUB][4];
    #pragma unroll
    for (int i = 0; i < NSUB; i++) { c[i][0] = c[i][1] = c[i][2] = c[i][3] = 0.f; }

    float4   aPre[CH];
    unsigned bPre[BE];

    auto loadA = [&](int kk, int e) -> float4 {
        int idx = tid + e * 256;
        int r = idx / CW, c4 = idx % CW;
        size_t off = (size_t)r * K + kk + c4 * 4;
        float4 acc = *(const float4*)(b2 + kk + c4 * 4);
        #pragma unroll
        for (int p = 0; p < KSPLIT2; p++) {
            float4 v = *(const float4*)(part2 + (size_t)p * 128 * K + off);
            acc.x += v.x; acc.y += v.y; acc.z += v.z; acc.w += v.w;
        }
        acc.x = fmaxf(acc.x, 0.f); acc.y = fmaxf(acc.y, 0.f);
        acc.z = fmaxf(acc.z, 0.f); acc.w = fmaxf(acc.w, 0.f);
        return acc;
    };

    #pragma unroll
    for (int e = 0; e < CH; e++) aPre[e] = loadA(k_begin, e);
    #pragma unroll
    for (int e = 0; e < BE; e++) {
        int idx = tid + e * 256;
        int kr = idx / BN, n = idx % BN;
        bPre[e] = __float_as_uint(B[(size_t)(k_begin + kr) * N + n]);
    }
    #pragma unroll
    for (int e = 0; e < CH; e++) {
        int idx = tid + e * 256;
        int r = idx / CW, c4 = idx % CW;
        As[r][c4 * 4 + 0] = __float_as_uint(aPre[e].x);
        As[r][c4 * 4 + 1] = __float_as_uint(aPre[e].y);
        As[r][c4 * 4 + 2] = __float_as_uint(aPre[e].z);
        As[r][c4 * 4 + 3] = __float_as_uint(aPre[e].w);
    }
    #pragma unroll
    for (int e = 0; e < BE; e++) {
        int idx = tid + e * 256;
        Bs[idx / BN][idx % BN] = bPre[e];
    }
    __syncthreads();

    int row = 16 * warp + grp;
    #pragma unroll 1
    for (int ch = 0; ch < NCH; ch++) {
        if (ch + 1 < NCH) {
            int kk = k_begin + (ch + 1) * KC;
            #pragma unroll
            for (int e = 0; e < CH; e++) aPre[e] = loadA(kk, e);
            #pragma unroll
            for (int e = 0; e < BE; e++) {
                int idx = tid + e * 256;
                int kr = idx / BN, n = idx % BN;
                bPre[e] = __float_as_uint(B[(size_t)(kk + kr) * N + n]);
            }
        }
        #pragma unroll
        for (int m = 0; m < CH; m++) {
            int k0 = m * 8;
            unsigned a0 = As[row][k0 + tig];
            unsigned a1 = As[row + 8][k0 + tig];
            unsigned a2 = As[row][k0 + tig + 4];
            unsigned a3 = As[row + 8][k0 + tig + 4];
            #pragma unroll
            for (int ns = 0; ns < NSUB; ns++) {
                unsigned b0 = Bs[k0 + tig][ns * 8 + grp];
                unsigned b1 = Bs[k0 + tig + 4][ns * 8 + grp];
                mma8(c[ns][0], c[ns][1], c[ns][2], c[ns][3], a0, a1, a2, a3, b0, b1);
            }
        }
        __syncthreads();
        if (ch + 1 < NCH) {
            #pragma unroll
            for (int e = 0; e < CH; e++) {
                int idx = tid + e * 256;
                int r = idx / CW, c4 = idx % CW;
                As[r][c4 * 4 + 0] = __float_as_uint(aPre[e].x);
                As[r][c4 * 4 + 1] = __float_as_uint(aPre[e].y);
                As[r][c4 * 4 + 2] = __float_as_uint(aPre[e].z);
                As[r][c4 * 4 + 3] = __float_as_uint(aPre[e].w);
            }
            #pragma unroll
            for (int e = 0; e < BE; e++) {
                int idx = tid + e * 256;
                Bs[idx / BN][idx % BN] = bPre[e];
            }
            __syncthreads();
        }
    }
    float* pout = part3 + (size_t)blockIdx.y * 128 * N;
    #pragma unroll
    for (int ns = 0; ns < NSUB; ns++) {
        int col = ns * 8 + tig * 2;
        pout[row * N + col]           = c[ns][0];
        pout[row * N + col + 1]       = c[ns][1];
        pout[(row + 8) * N + col]     = c[ns][2];
        pout[(row + 8) * N + col + 1] = c[ns][3];
    }
}

__global__ void reduce_bias_relu_k(const float* __restrict__ part,
                                   const float* __restrict__ bias,
                                   float* __restrict__ out, int N, int ksplit) {
    int idx = blockIdx.x * 256 + threadIdx.x;
    if (idx >= 128 * N) return;
    int n = idx % N;
    float s = bias[n];
    for (int k = 0; k < ksplit; k++) s += part[k * 128 * N + idx];
    out[idx] = fmaxf(s, 0.f);
}

// ---------------- layer-3 reduce + classifier head + output pack + state reset ----------------
__global__ void head3_k(const float* __restrict__ b3,
                        const float* __restrict__ wc, const float* __restrict__ bc,
                        float* __restrict__ out, int out_size) {
    int s = threadIdx.x;   // 128 segments
    float l0 = bc[0], l1 = bc[1];
    #pragma unroll
    for (int j = 0; j < D_LOW; j++) {
        float a = b3[j];
        #pragma unroll
        for (int k = 0; k < KSPLIT2; k++) a += g_part3[k * 128 * D_LOW + s * D_LOW + j];
        float h = fmaxf(a, 0.f);
        l0 += h * wc[j * 2 + 0];
        l1 += h * wc[j * 2 + 1];
    }
    float m = fmaxf(l0, l1);
    float e0 = expf(l0 - m), e1 = expf(l1 - m);
    float inv = 1.f / (e0 + e1);
    out[2 * s]     = e0 * inv;
    out[2 * s + 1] = e1 * inv;
    if (out_size >= 384) out[256 + s] = (float)g_lab2[s];
    // reset device state for next graph replay
    if (s == 0) { g_bar1 = 0; g_flag1 = 0; }
    g_cls[s * 3 + 0] = 0; g_cls[s * 3 + 1] = 0; g_cls[s * 3 + 2] = 0;
}

// ---------------- launch ----------------
extern "C" void kernel_launch(void* const* d_in, const int* in_sizes, int n_in,
                              void* d_out, int out_size) {
    const float* pixfeat = (const float*)d_in[0];
    const float* w1 = (const float*)d_in[1];
    const float* b1 = (const float*)d_in[2];
    const float* w2 = (const float*)d_in[3];
    const float* b2 = (const float*)d_in[4];
    const float* w3 = (const float*)d_in[5];
    const float* b3 = (const float*)d_in[6];
    const float* wc = (const float*)d_in[7];
    const float* bc = (const float*)d_in[8];
    const int*   sp = (const int*)d_in[9];
    const int*   yy = (const int*)d_in[10];
    float* out = (float*)d_out;

    float *p_feat, *p_h1, *p_part, *p_part3;
    cudaGetSymbolAddress((void**)&p_feat,  g_feat);
    cudaGetSymbolAddress((void**)&p_h1,    g_h1);
    cudaGetSymbolAddress((void**)&p_part,  g_part);
    cudaGetSymbolAddress((void**)&p_part3, g_part3);

    cudaStream_t sB;
    cudaStreamCreateWithFlags(&sB, cudaStreamNonBlocking);
    cudaEvent_t eA, eB;
    cudaEventCreateWithFlags(&eA, cudaEventDisableTiming);
    cudaEventCreateWithFlags(&eB, cudaEventDisableTiming);

    prep_k<<<NBLK, 256>>>(sp, yy);
    segsum_k<<<dim3(NCB, NSEG), 128>>>(pixfeat);

    // fork: affinity/label propagation runs concurrently with the MLP chain
    cudaEventRecord(eA, 0);
    cudaStreamWaitEvent(sB, eA, 0);
    aff_k<<<64, 128, 0, sB>>>();
    cudaEventRecord(eB, sB);

    // MLP chain on main stream
    gemm_tf32_k<8, 3, 11><<<dim3(D_HID / 64, KSPLIT1), 256>>>(p_feat, w1, p_part, D_HID, C_FEAT);
    reduce_bias_relu_k<<<(128 * D_HID + 255) / 256, 256>>>(p_part, b1, p_h1, D_HID, KSPLIT1);
    gemm_tf32_k<8, 4, 4><<<dim3(D_HID / 64, KSPLIT2), 256>>>(p_h1, w2, p_part, D_HID, D_HID);
    gemm3f_k<<<dim3(1, KSPLIT2), 256>>>(p_part, b2, w3, p_part3);

    cudaStreamWaitEvent((cudaStream_t)0, eB, 0);
    head3_k<<<1, 128>>>(b3, wc, bc, out, out_size);
}